// round 1
// baseline (speedup 1.0000x reference)
#include <cuda_runtime.h>
#include <math.h>
#include <float.h>

#define TPB   256
#define KNN_K 16
#define FULLM 0xFFFFFFFFu

// scratch (static device arrays; allocation-free rule)
__device__ int                g_idx [65536 * KNN_K];
__device__ float              g_w   [65536 * KNN_K];
__device__ float              g_Dfwd[65536];
__device__ unsigned long long g_Drev[65536];

__device__ __forceinline__ bool lex_less(float d, int j, float D, int J) {
    // matches lax.top_k ordering on (-d2): smaller d2 first, ties -> smaller index
    return (d < D) || ((d == D) && (j < J));
}

// Fused kernel: blocks [0, nb_knn) do KNN (2 queries per warp, ballot top-16);
// blocks [nb_knn, nb_knn + B*N) zero the dense L and set the diagonal to 1.
__global__ void k_knn_init(const float* __restrict__ xyz,
                           float* __restrict__ out,
                           int N, int B, int nb_knn)
{
    extern __shared__ float4 cand[];   // N entries: (x, y, z, |p|^2)
    const int tid = threadIdx.x;

    if ((int)blockIdx.x >= nb_knn) {
        // ---------------- memset + diagonal path ----------------
        int bid = blockIdx.x - nb_knn;          // 0 .. B*N-1 : one row each
        int b = bid / N;
        int i = bid - b * N;
        float4* row = reinterpret_cast<float4*>(out + ((size_t)b * N + i) * (size_t)N);
        int n4 = N >> 2;
        for (int f = tid; f < n4; f += TPB) {
            int j0 = f << 2;
            float4 v;
            v.x = (j0     == i) ? 1.0f : 0.0f;
            v.y = (j0 + 1 == i) ? 1.0f : 0.0f;
            v.z = (j0 + 2 == i) ? 1.0f : 0.0f;
            v.w = (j0 + 3 == i) ? 1.0f : 0.0f;
            row[f] = v;
        }
        return;
    }

    // ---------------- KNN path ----------------
    const int qpb = (TPB / 32) * 2;             // 16 queries per block
    const int blocks_per_b = N / qpb;
    const int b = blockIdx.x / blocks_per_b;
    const int qbase = (blockIdx.x - b * blocks_per_b) * qpb;

    const float* X = xyz + (size_t)b * 3 * N;
    for (int n = tid; n < N; n += TPB) {
        float x = X[n], y = X[N + n], z = X[2 * N + n];
        float sq = fmaf(x, x, fmaf(y, y, z * z));
        cand[n] = make_float4(x, y, z, sq);
    }
    __syncthreads();

    const int warp = tid >> 5, lane = tid & 31;
    const int g = lane >> 4, sub = lane & 15;
    const int q0i = qbase + warp * 2;
    const float4 q0 = cand[q0i];
    const float4 q1 = cand[q0i + 1];

    // sorted-across-lanes top-16 for this lane's group's query
    float ld = FLT_MAX; int li = 0x7FFFFFFF;
    // warp-uniform current worst (rank-15) per query
    float wd0 = FLT_MAX, wd1 = FLT_MAX;
    int   wi0 = 0x7FFFFFFF, wi1 = 0x7FFFFFFF;

    for (int base = 0; base < N; base += 32) {
        const int j = base + lane;
        const float4 c = cand[j];
        float dot0 = fmaf(q0.x, c.x, fmaf(q0.y, c.y, q0.z * c.z));
        float d0   = fmaf(-2.0f, dot0, q0.w + c.w);
        float dot1 = fmaf(q1.x, c.x, fmaf(q1.y, c.y, q1.z * c.z));
        float d1   = fmaf(-2.0f, dot1, q1.w + c.w);

        unsigned bal0 = __ballot_sync(FULLM, lex_less(d0, j, wd0, wi0));
        unsigned bal1 = __ballot_sync(FULLM, lex_less(d1, j, wd1, wi1));

        while (bal0) {
            int src = __ffs(bal0) - 1; bal0 &= bal0 - 1;
            float dd = __shfl_sync(FULLM, d0, src);
            int   jj = base + src;
            bool pr = (g == 0) && lex_less(dd, jj, ld, li);
            unsigned pb = __ballot_sync(FULLM, pr);
            float sld = __shfl_up_sync(FULLM, ld, 1);
            int   sli = __shfl_up_sync(FULLM, li, 1);
            bool prevpr = (sub > 0) && ((pb >> (lane - 1)) & 1u);
            if (pr) { ld = prevpr ? sld : dd; li = prevpr ? sli : jj; }
            wd0 = __shfl_sync(FULLM, ld, 15);
            wi0 = __shfl_sync(FULLM, li, 15);
        }
        while (bal1) {
            int src = __ffs(bal1) - 1; bal1 &= bal1 - 1;
            float dd = __shfl_sync(FULLM, d1, src);
            int   jj = base + src;
            bool pr = (g == 1) && lex_less(dd, jj, ld, li);
            unsigned pb = __ballot_sync(FULLM, pr);
            float sld = __shfl_up_sync(FULLM, ld, 1);
            int   sli = __shfl_up_sync(FULLM, li, 1);
            bool prevpr = (sub > 0) && ((pb >> (lane - 1)) & 1u);
            if (pr) { ld = prevpr ? sld : dd; li = prevpr ? sli : jj; }
            wd1 = __shfl_sync(FULLM, ld, 31);
            wi1 = __shfl_sync(FULLM, li, 31);
        }
    }

    // epilogue: exact weight recomputation (faithful to reference)
    const float4 qq = g ? q1 : q0;
    const int qli = q0i + g;
    const float4 nb = cand[li];
    float dx = qq.x - nb.x, dy = qq.y - nb.y, dz = qq.z - nb.z;
    float dist2 = fmaf(dx, dx, fmaf(dy, dy, dz * dz));
    float w = expf(-0.5f * dist2);

    const int qglob = b * N + qli;
    g_idx[qglob * KNN_K + sub] = li;
    g_w [qglob * KNN_K + sub] = w;

    float s = w;
    s += __shfl_xor_sync(FULLM, s, 8);
    s += __shfl_xor_sync(FULLM, s, 4);
    s += __shfl_xor_sync(FULLM, s, 2);
    s += __shfl_xor_sync(FULLM, s, 1);
    if (sub == 0) {
        g_Dfwd[qglob] = 0.5f * s;
        g_Drev[qglob] = 0ull;
    }
}

// Reverse-degree scatter with integer fixed-point atomics (deterministic).
__global__ void k_drev(int N, int total_edges)
{
    int e = blockIdx.x * blockDim.x + threadIdx.x;
    if (e >= total_edges) return;
    int q = e >> 4;                 // KNN_K == 16
    int b = q / N;
    float w = g_w[e];
    unsigned long long inc = (unsigned long long)((double)w * 4294967296.0);
    atomicAdd(&g_Drev[b * N + g_idx[e]], inc);
}

// Sparse Laplacian scatter: each directed edge contributes
// -(d_i * 0.5*w * d_j) to L[i][j] and L[j][i]. Diagonal handled by self edge.
__global__ void k_scatter(float* __restrict__ out, int N, int total_edges)
{
    int e = blockIdx.x * blockDim.x + threadIdx.x;
    if (e >= total_edges) return;
    int q = e >> 4;
    int b = q / N;
    int i = q - b * N;
    int j = g_idx[e];
    float w = g_w[e];

    float Di = g_Dfwd[q]         + (float)((double)g_Drev[q]         * (0.5 / 4294967296.0));
    float Dj = g_Dfwd[b * N + j] + (float)((double)g_Drev[b * N + j] * (0.5 / 4294967296.0));
    float di = 1.0f / sqrtf(fmaxf(Di, 1e-6f));
    float dj = 1.0f / sqrtf(fmaxf(Dj, 1e-6f));
    float v = -((0.5f * w) * di) * dj;

    float* Lb = out + (size_t)b * N * (size_t)N;
    atomicAdd(Lb + (size_t)i * N + j, v);
    atomicAdd(Lb + (size_t)j * N + i, v);
}

extern "C" void kernel_launch(void* const* d_in, const int* in_sizes, int n_in,
                              void* d_out, int out_size)
{
    const float* xyz = (const float*)d_in[0];
    float* out = (float*)d_out;

    long long inel = in_sizes[0];                       // B*3*N
    int N = (int)((3LL * (long long)out_size) / inel);  // (3*B*N^2)/(3*B*N)
    int B = (int)(inel / (3LL * (long long)N));

    int nb_knn = B * (N / 16);        // KNN blocks (16 queries each)
    int nb_set = B * N;               // one block per output row
    size_t smem = (size_t)N * sizeof(float4);

    cudaFuncSetAttribute(k_knn_init, cudaFuncAttributeMaxDynamicSharedMemorySize, (int)smem);
    k_knn_init<<<nb_knn + nb_set, TPB, smem>>>(xyz, out, N, B, nb_knn);

    int edges = B * N * KNN_K;
    int eb = (edges + TPB - 1) / TPB;
    k_drev<<<eb, TPB>>>(N, edges);
    k_scatter<<<eb, TPB>>>(out, N, edges);
}

// round 2
// speedup vs baseline: 1.8158x; 1.8158x over previous
#include <cuda_runtime.h>
#include <math.h>
#include <float.h>

#define TPB   512
#define KNN_K 16
#define FULLM 0xFFFFFFFFu

// scratch (static device arrays; allocation-free rule)
__device__ int                g_idx [65536 * KNN_K];
__device__ float              g_w   [65536 * KNN_K];
__device__ float              g_Dfwd[65536];
__device__ unsigned long long g_Drev[65536];

__device__ __forceinline__ bool lex_less(float d, int j, float D, int J) {
    // matches lax.top_k ordering on (-d2): smaller d2 first, ties -> smaller index
    return (d < D) || ((d == D) && (j < J));
}

// Fused kernel: blocks [0, nb_knn) do KNN (32 queries per block, 2 per warp,
// ballot top-16 with interleaved dual-drain); blocks [nb_knn, nb_knn + B*N)
// zero the dense L and set the diagonal to 1.
__global__ void __launch_bounds__(TPB)
k_knn_init(const float* __restrict__ xyz,
           float* __restrict__ out,
           int N, int B, int nb_knn)
{
    extern __shared__ float4 cand[];   // N entries: (x, y, z, |p|^2)
    const int tid = threadIdx.x;

    if ((int)blockIdx.x >= nb_knn) {
        // ---------------- memset + diagonal path ----------------
        int bid = blockIdx.x - nb_knn;          // 0 .. B*N-1 : one row each
        int b = bid / N;
        int i = bid - b * N;
        float4* row = reinterpret_cast<float4*>(out + ((size_t)b * N + i) * (size_t)N);
        int n4 = N >> 2;
        for (int f = tid; f < n4; f += TPB) {
            int j0 = f << 2;
            float4 v;
            v.x = (j0     == i) ? 1.0f : 0.0f;
            v.y = (j0 + 1 == i) ? 1.0f : 0.0f;
            v.z = (j0 + 2 == i) ? 1.0f : 0.0f;
            v.w = (j0 + 3 == i) ? 1.0f : 0.0f;
            row[f] = v;
        }
        return;
    }

    // ---------------- KNN path ----------------
    const int qpb = (TPB / 32) * 2;             // 32 queries per block
    const int blocks_per_b = N / qpb;
    const int b = blockIdx.x / blocks_per_b;
    const int qbase = (blockIdx.x - b * blocks_per_b) * qpb;

    const float* X = xyz + (size_t)b * 3 * N;
    for (int n = tid; n < N; n += TPB) {
        float x = X[n], y = X[N + n], z = X[2 * N + n];
        float sq = fmaf(x, x, fmaf(y, y, z * z));
        cand[n] = make_float4(x, y, z, sq);
    }
    __syncthreads();

    const int warp = tid >> 5, lane = tid & 31;
    const int g = lane >> 4, sub = lane & 15;
    const int q0i = qbase + warp * 2;
    const float4 q0 = cand[q0i];
    const float4 q1 = cand[q0i + 1];

    // sorted-across-lanes top-16: lanes 0-15 hold q0's list, 16-31 hold q1's
    float ld = FLT_MAX; int li = 0x7FFFFFFF;
    // warp-uniform current worst (rank-15) per query (stale within a chunk: OK)
    float wd0 = FLT_MAX, wd1 = FLT_MAX;
    int   wi0 = 0x7FFFFFFF, wi1 = 0x7FFFFFFF;

    for (int base = 0; base < N; base += 32) {
        const int j = base + lane;
        const float4 c = cand[j];
        float dot0 = fmaf(q0.x, c.x, fmaf(q0.y, c.y, q0.z * c.z));
        float d0   = fmaf(-2.0f, dot0, q0.w + c.w);
        float dot1 = fmaf(q1.x, c.x, fmaf(q1.y, c.y, q1.z * c.z));
        float d1   = fmaf(-2.0f, dot1, q1.w + c.w);

        unsigned bal0 = __ballot_sync(FULLM, lex_less(d0, j, wd0, wi0));
        unsigned bal1 = __ballot_sync(FULLM, lex_less(d1, j, wd1, wi1));
        if ((bal0 | bal1) == 0u) continue;

        // interleaved drain: one insert for each query per iteration
        do {
            int s0 = __ffs(bal0) - 1;           // -1 when empty
            int s1 = __ffs(bal1) - 1;
            float dd0 = __shfl_sync(FULLM, d0, s0 & 31);
            float dd1 = __shfl_sync(FULLM, d1, s1 & 31);
            bool have = g ? (bal1 != 0u) : (bal0 != 0u);
            float dd = g ? dd1 : dd0;
            int   jj = base + ((g ? s1 : s0) & 31);

            bool pr = have && lex_less(dd, jj, ld, li);
            unsigned pb = __ballot_sync(FULLM, pr);
            float sld = __shfl_up_sync(FULLM, ld, 1);
            int   sli = __shfl_up_sync(FULLM, li, 1);
            bool prevpr = (sub > 0) && ((pb >> (lane - 1)) & 1u);
            if (pr) { ld = prevpr ? sld : dd; li = prevpr ? sli : jj; }

            bal0 &= bal0 - 1;                   // 0 stays 0
            bal1 &= bal1 - 1;
        } while (bal0 | bal1);

        // threshold refresh once per chunk (only consumed by next ballot)
        wd0 = __shfl_sync(FULLM, ld, 15);
        wi0 = __shfl_sync(FULLM, li, 15);
        wd1 = __shfl_sync(FULLM, ld, 31);
        wi1 = __shfl_sync(FULLM, li, 31);
    }

    // epilogue: exact weight recomputation (faithful to reference)
    const float4 qq = g ? q1 : q0;
    const int qli = q0i + g;
    const float4 nb = cand[li];
    float dx = qq.x - nb.x, dy = qq.y - nb.y, dz = qq.z - nb.z;
    float dist2 = fmaf(dx, dx, fmaf(dy, dy, dz * dz));
    float w = expf(-0.5f * dist2);

    const int qglob = b * N + qli;
    g_idx[qglob * KNN_K + sub] = li;
    g_w [qglob * KNN_K + sub] = w;

    float s = w;
    s += __shfl_xor_sync(FULLM, s, 8);
    s += __shfl_xor_sync(FULLM, s, 4);
    s += __shfl_xor_sync(FULLM, s, 2);
    s += __shfl_xor_sync(FULLM, s, 1);
    if (sub == 0) {
        g_Dfwd[qglob] = 0.5f * s;
        g_Drev[qglob] = 0ull;
    }
}

// Reverse-degree scatter with integer fixed-point atomics (deterministic).
__global__ void k_drev(int N, int total_edges)
{
    int e = blockIdx.x * blockDim.x + threadIdx.x;
    if (e >= total_edges) return;
    int q = e >> 4;                 // KNN_K == 16
    int b = q / N;
    float w = g_w[e];
    unsigned long long inc = (unsigned long long)((double)w * 4294967296.0);
    atomicAdd(&g_Drev[b * N + g_idx[e]], inc);
}

// Sparse Laplacian scatter: each directed edge contributes
// -(d_i * 0.5*w * d_j) to L[i][j] and L[j][i]. Diagonal handled by self edge.
__global__ void k_scatter(float* __restrict__ out, int N, int total_edges)
{
    int e = blockIdx.x * blockDim.x + threadIdx.x;
    if (e >= total_edges) return;
    int q = e >> 4;
    int b = q / N;
    int i = q - b * N;
    int j = g_idx[e];
    float w = g_w[e];

    float Di = g_Dfwd[q]         + (float)((double)g_Drev[q]         * (0.5 / 4294967296.0));
    float Dj = g_Dfwd[b * N + j] + (float)((double)g_Drev[b * N + j] * (0.5 / 4294967296.0));
    float di = 1.0f / sqrtf(fmaxf(Di, 1e-6f));
    float dj = 1.0f / sqrtf(fmaxf(Dj, 1e-6f));
    float v = -((0.5f * w) * di) * dj;

    float* Lb = out + (size_t)b * N * (size_t)N;
    atomicAdd(Lb + (size_t)i * N + j, v);
    atomicAdd(Lb + (size_t)j * N + i, v);
}

extern "C" void kernel_launch(void* const* d_in, const int* in_sizes, int n_in,
                              void* d_out, int out_size)
{
    const float* xyz = (const float*)d_in[0];
    float* out = (float*)d_out;

    long long inel = in_sizes[0];                       // B*3*N
    int N = (int)((3LL * (long long)out_size) / inel);  // (3*B*N^2)/(3*B*N)
    int B = (int)(inel / (3LL * (long long)N));

    int nb_knn = B * (N / 32);        // KNN blocks (32 queries each)
    int nb_set = B * N;               // one block per output row
    size_t smem = (size_t)N * sizeof(float4);

    cudaFuncSetAttribute(k_knn_init, cudaFuncAttributeMaxDynamicSharedMemorySize, (int)smem);
    k_knn_init<<<nb_knn + nb_set, TPB, smem>>>(xyz, out, N, B, nb_knn);

    int edges = B * N * KNN_K;
    int eb = (edges + 255) / 256;
    k_drev<<<eb, 256>>>(N, edges);
    k_scatter<<<eb, 256>>>(out, N, edges);
}

// round 3
// speedup vs baseline: 2.0602x; 1.1346x over previous
#include <cuda_runtime.h>
#include <math.h>
#include <float.h>

#define TPB   512
#define KNN_K 16
#define FULLM 0xFFFFFFFFu

// scratch (static device arrays; allocation-free rule)
__device__ int                g_idx [65536 * KNN_K];
__device__ float              g_w   [65536 * KNN_K];
__device__ float              g_Dfwd[65536];
__device__ unsigned long long g_Drev[65536];

// Fused kernel: blocks [0, nb_knn) do KNN (32 queries per block, 2 per warp,
// e-space ballot top-16, 64-candidate chunks); blocks [nb_knn, ...) zero the
// dense L and set the diagonal to 1.
__global__ void __launch_bounds__(TPB)
k_knn_init(const float* __restrict__ xyz,
           float* __restrict__ out,
           int N, int B, int nb_knn)
{
    extern __shared__ float4 cand[];   // N entries: (x, y, z, |p|^2)
    const int tid = threadIdx.x;

    if ((int)blockIdx.x >= nb_knn) {
        // ---------------- memset + diagonal path ----------------
        int bid = blockIdx.x - nb_knn;          // 0 .. B*N-1 : one row each
        int b = bid / N;
        int i = bid - b * N;
        float4* row = reinterpret_cast<float4*>(out + ((size_t)b * N + i) * (size_t)N);
        int n4 = N >> 2;
        for (int f = tid; f < n4; f += TPB) {
            int j0 = f << 2;
            float4 v;
            v.x = (j0     == i) ? 1.0f : 0.0f;
            v.y = (j0 + 1 == i) ? 1.0f : 0.0f;
            v.z = (j0 + 2 == i) ? 1.0f : 0.0f;
            v.w = (j0 + 3 == i) ? 1.0f : 0.0f;
            row[f] = v;
        }
        return;
    }

    // ---------------- KNN path ----------------
    const int qpb = (TPB / 32) * 2;             // 32 queries per block
    const int blocks_per_b = N / qpb;
    const int b = blockIdx.x / blocks_per_b;
    const int qbase = (blockIdx.x - b * blocks_per_b) * qpb;

    const float* X = xyz + (size_t)b * 3 * N;
    for (int n = tid; n < N; n += TPB) {
        float x = X[n], y = X[N + n], z = X[2 * N + n];
        float sq = fmaf(x, x, fmaf(y, y, z * z));
        cand[n] = make_float4(x, y, z, sq);
    }
    __syncthreads();

    const int warp = tid >> 5, lane = tid & 31;
    const int g = lane >> 4, sub = lane & 15;
    const int q0i = qbase + warp * 2;
    const float4 q0 = cand[q0i];
    const float4 q1 = cand[q0i + 1];

    // pre-scaled queries: e = fma(a.x,c.x, fma(a.y,c.y, fma(a.z,c.z, c.w)))
    //                       = |c|^2 - 2 q.c  = d^2 - |q|^2  (monotone in d^2)
    const float a0x = -2.0f * q0.x, a0y = -2.0f * q0.y, a0z = -2.0f * q0.z;
    const float a1x = -2.0f * q1.x, a1y = -2.0f * q1.y, a1z = -2.0f * q1.z;

    // sorted-across-lanes top-16 in e-space: lanes 0-15 = q0, 16-31 = q1
    float ld = FLT_MAX; int li = 0x7FFFFFFF;
    // warp-uniform screening thresholds (rank-15 e per query; stale-safe)
    float wt0 = FLT_MAX, wt1 = FLT_MAX;

    #pragma unroll 1
    for (int base = 0; base < N; base += 64) {
        const float4 cA = cand[base + lane];
        const float4 cB = cand[base + 32 + lane];
        float eA0 = fmaf(a0x, cA.x, fmaf(a0y, cA.y, fmaf(a0z, cA.z, cA.w)));
        float eA1 = fmaf(a1x, cA.x, fmaf(a1y, cA.y, fmaf(a1z, cA.z, cA.w)));
        float eB0 = fmaf(a0x, cB.x, fmaf(a0y, cB.y, fmaf(a0z, cB.z, cB.w)));
        float eB1 = fmaf(a1x, cB.x, fmaf(a1y, cB.y, fmaf(a1z, cB.z, cB.w)));

        unsigned balA0 = __ballot_sync(FULLM, eA0 < wt0);
        unsigned balA1 = __ballot_sync(FULLM, eA1 < wt1);
        unsigned balB0 = __ballot_sync(FULLM, eB0 < wt0);
        unsigned balB1 = __ballot_sync(FULLM, eB1 < wt1);
        if ((balA0 | balA1 | balB0 | balB1) == 0u) continue;

        // drain A half (candidates base..base+31), dual-query interleaved
        while (balA0 | balA1) {
            int s0 = __ffs(balA0) - 1;
            int s1 = __ffs(balA1) - 1;
            float dd0 = __shfl_sync(FULLM, eA0, s0 & 31);
            float dd1 = __shfl_sync(FULLM, eA1, s1 & 31);
            bool have = g ? (balA1 != 0u) : (balA0 != 0u);
            float dd = g ? dd1 : dd0;
            int   jj = base + ((g ? s1 : s0) & 31);

            bool pr = have && (dd < ld);        // strict: index order => lex
            unsigned pb = __ballot_sync(FULLM, pr);
            float sld = __shfl_up_sync(FULLM, ld, 1);
            int   sli = __shfl_up_sync(FULLM, li, 1);
            bool prevpr = (sub > 0) && ((pb >> (lane - 1)) & 1u);
            if (pr) { ld = prevpr ? sld : dd; li = prevpr ? sli : jj; }

            balA0 &= balA0 - 1;
            balA1 &= balA1 - 1;
        }
        // drain B half (candidates base+32..base+63)
        while (balB0 | balB1) {
            int s0 = __ffs(balB0) - 1;
            int s1 = __ffs(balB1) - 1;
            float dd0 = __shfl_sync(FULLM, eB0, s0 & 31);
            float dd1 = __shfl_sync(FULLM, eB1, s1 & 31);
            bool have = g ? (balB1 != 0u) : (balB0 != 0u);
            float dd = g ? dd1 : dd0;
            int   jj = base + 32 + ((g ? s1 : s0) & 31);

            bool pr = have && (dd < ld);
            unsigned pb = __ballot_sync(FULLM, pr);
            float sld = __shfl_up_sync(FULLM, ld, 1);
            int   sli = __shfl_up_sync(FULLM, li, 1);
            bool prevpr = (sub > 0) && ((pb >> (lane - 1)) & 1u);
            if (pr) { ld = prevpr ? sld : dd; li = prevpr ? sli : jj; }

            balB0 &= balB0 - 1;
            balB1 &= balB1 - 1;
        }

        // threshold refresh once per chunk (only consumed by next ballots)
        wt0 = __shfl_sync(FULLM, ld, 15);
        wt1 = __shfl_sync(FULLM, ld, 31);
    }

    // epilogue: exact weight recomputation (faithful to reference)
    const float4 qq = g ? q1 : q0;
    const int qli = q0i + g;
    const float4 nb = cand[li];
    float dx = qq.x - nb.x, dy = qq.y - nb.y, dz = qq.z - nb.z;
    float dist2 = fmaf(dx, dx, fmaf(dy, dy, dz * dz));
    float w = expf(-0.5f * dist2);

    const int qglob = b * N + qli;
    g_idx[qglob * KNN_K + sub] = li;
    g_w [qglob * KNN_K + sub] = w;

    float s = w;
    s += __shfl_xor_sync(FULLM, s, 8);
    s += __shfl_xor_sync(FULLM, s, 4);
    s += __shfl_xor_sync(FULLM, s, 2);
    s += __shfl_xor_sync(FULLM, s, 1);
    if (sub == 0) {
        g_Dfwd[qglob] = 0.5f * s;
        g_Drev[qglob] = 0ull;
    }
}

// Reverse-degree scatter with integer fixed-point atomics (deterministic).
__global__ void k_drev(int N, int total_edges)
{
    int e = blockIdx.x * blockDim.x + threadIdx.x;
    if (e >= total_edges) return;
    int q = e >> 4;                 // KNN_K == 16
    int b = q / N;
    float w = g_w[e];
    unsigned long long inc = (unsigned long long)((double)w * 4294967296.0);
    atomicAdd(&g_Drev[b * N + g_idx[e]], inc);
}

// Sparse Laplacian scatter: each directed edge contributes
// -(d_i * 0.5*w * d_j) to L[i][j] and L[j][i]. Diagonal handled by self edge.
__global__ void k_scatter(float* __restrict__ out, int N, int total_edges)
{
    int e = blockIdx.x * blockDim.x + threadIdx.x;
    if (e >= total_edges) return;
    int q = e >> 4;
    int b = q / N;
    int i = q - b * N;
    int j = g_idx[e];
    float w = g_w[e];

    float Di = g_Dfwd[q]         + (float)((double)g_Drev[q]         * (0.5 / 4294967296.0));
    float Dj = g_Dfwd[b * N + j] + (float)((double)g_Drev[b * N + j] * (0.5 / 4294967296.0));
    float di = 1.0f / sqrtf(fmaxf(Di, 1e-6f));
    float dj = 1.0f / sqrtf(fmaxf(Dj, 1e-6f));
    float v = -((0.5f * w) * di) * dj;

    float* Lb = out + (size_t)b * N * (size_t)N;
    atomicAdd(Lb + (size_t)i * N + j, v);
    atomicAdd(Lb + (size_t)j * N + i, v);
}

extern "C" void kernel_launch(void* const* d_in, const int* in_sizes, int n_in,
                              void* d_out, int out_size)
{
    const float* xyz = (const float*)d_in[0];
    float* out = (float*)d_out;

    long long inel = in_sizes[0];                       // B*3*N
    int N = (int)((3LL * (long long)out_size) / inel);  // (3*B*N^2)/(3*B*N)
    int B = (int)(inel / (3LL * (long long)N));

    int nb_knn = B * (N / 32);        // KNN blocks (32 queries each)
    int nb_set = B * N;               // one block per output row
    size_t smem = (size_t)N * sizeof(float4);

    cudaFuncSetAttribute(k_knn_init, cudaFuncAttributeMaxDynamicSharedMemorySize, (int)smem);
    k_knn_init<<<nb_knn + nb_set, TPB, smem>>>(xyz, out, N, B, nb_knn);

    int edges = B * N * KNN_K;
    int eb = (edges + 255) / 256;
    k_drev<<<eb, 256>>>(N, edges);
    k_scatter<<<eb, 256>>>(out, N, edges);
}

// round 4
// speedup vs baseline: 2.1474x; 1.0423x over previous
#include <cuda_runtime.h>
#include <math.h>
#include <float.h>

#define TPB    512
#define KNN_K  16
#define NBUCK  64
#define FULLM  0xFFFFFFFFu
#define XMIN   (-4.8f)
#define XMAX   ( 4.8f)
#define BW     ((XMAX - XMIN) / (float)NBUCK)
#define INVBW  ((float)NBUCK / (XMAX - XMIN))
#define SAFE   1e-5f

// scratch (static device arrays; allocation-free rule)
__device__ int                g_idx [65536 * KNN_K];
__device__ float              g_w   [65536 * KNN_K];
__device__ float              g_Dfwd[65536];
__device__ unsigned long long g_Drev[65536];

// bucket-build scratch
__device__ int            g_hist[16 * NBUCK];        // zero-init; re-zeroed by k_scan
__device__ int            g_off [16 * (NBUCK + 1)];
__device__ int            g_cur [16 * NBUCK];
__device__ float4         g_rc  [65536];             // reordered (x,y,z,|p|^2)
__device__ unsigned short g_rid [65536];             // orig index per position

__device__ __forceinline__ int bucket_of_x(float x) {
    int ib = (int)((x - XMIN) * INVBW);
    return min(max(ib, 0), NBUCK - 1);
}

// ---------- prepass ----------
__global__ void k_hist(const float* __restrict__ xyz, int N, int B)
{
    int t = blockIdx.x * blockDim.x + threadIdx.x;
    if (t >= B * N) return;
    int b = t / N, n = t - b * N;
    float x = xyz[(size_t)b * 3 * N + n];
    atomicAdd(&g_hist[b * NBUCK + bucket_of_x(x)], 1);
}

__global__ void k_scan(int B)
{
    int warp = threadIdx.x >> 5, lane = threadIdx.x & 31;
    if (warp >= B) return;
    int base = warp * NBUCK;
    int v0 = g_hist[base + lane];
    int v1 = g_hist[base + 32 + lane];
    int s0 = v0, s1 = v1;
    for (int d = 1; d < 32; d <<= 1) {
        int t0 = __shfl_up_sync(FULLM, s0, d);
        int t1 = __shfl_up_sync(FULLM, s1, d);
        if (lane >= d) { s0 += t0; s1 += t1; }
    }
    s1 += __shfl_sync(FULLM, s0, 31);
    int ob = warp * (NBUCK + 1);
    if (lane == 0) g_off[ob] = 0;
    g_off[ob + 1 + lane]  = s0;
    g_off[ob + 33 + lane] = s1;
    g_cur[base + lane]      = s0 - v0;
    g_cur[base + 32 + lane] = s1 - v1;
    g_hist[base + lane] = 0;                 // ready for next graph replay
    g_hist[base + 32 + lane] = 0;
}

__global__ void k_reorder(const float* __restrict__ xyz, int N, int B)
{
    int t = blockIdx.x * blockDim.x + threadIdx.x;
    if (t >= B * N) return;
    int b = t / N, n = t - b * N;
    const float* X = xyz + (size_t)b * 3 * N;
    float x = X[n], y = X[N + n], z = X[2 * N + n];
    float sq = fmaf(x, x, fmaf(y, y, z * z));
    int pos = atomicAdd(&g_cur[b * NBUCK + bucket_of_x(x)], 1);
    g_rc [b * N + pos] = make_float4(x, y, z, sq);
    g_rid[b * N + pos] = (unsigned short)n;
}

// ---------- fused KNN + dense init ----------
__global__ void __launch_bounds__(TPB, 3)
k_knn_init(float* __restrict__ out, int N, int B, int nb_knn)
{
    extern __shared__ char smraw[];
    const int tid = threadIdx.x;

    if ((int)blockIdx.x >= nb_knn) {
        // ---------------- memset + diagonal path ----------------
        int bid = blockIdx.x - nb_knn;
        int b = bid / N;
        int i = bid - b * N;
        float4* row = reinterpret_cast<float4*>(out + ((size_t)b * N + i) * (size_t)N);
        int n4 = N >> 2;
        for (int f = tid; f < n4; f += TPB) {
            int j0 = f << 2;
            float4 v;
            v.x = (j0     == i) ? 1.0f : 0.0f;
            v.y = (j0 + 1 == i) ? 1.0f : 0.0f;
            v.z = (j0 + 2 == i) ? 1.0f : 0.0f;
            v.w = (j0 + 3 == i) ? 1.0f : 0.0f;
            row[f] = v;
        }
        return;
    }

    // ---------------- KNN path ----------------
    float4*         rc  = reinterpret_cast<float4*>(smraw);            // N float4
    unsigned short* rid = reinterpret_cast<unsigned short*>(rc + N);   // N ushort
    int*            off = reinterpret_cast<int*>(rid + N);             // NBUCK+1

    const int qpb = (TPB / 32) * 2;             // 32 queries per block
    const int blocks_per_b = N / qpb;
    const int b = blockIdx.x / blocks_per_b;
    const int qbase = (blockIdx.x - b * blocks_per_b) * qpb;
    const int bN = b * N;

    for (int n = tid; n < N; n += TPB) rc[n]  = g_rc[bN + n];
    for (int n = tid; n < N; n += TPB) rid[n] = g_rid[bN + n];
    if (tid <= NBUCK) off[tid] = g_off[b * (NBUCK + 1) + tid];
    __syncthreads();

    const int warp = tid >> 5, lane = tid & 31;
    const int g = lane >> 4, sub = lane & 15;
    const int pos0 = qbase + warp * 2;          // bucket-sorted positions
    const float4 q0 = rc[pos0];
    const float4 q1 = rc[pos0 + 1];

    const float a0x = -2.0f * q0.x, a0y = -2.0f * q0.y, a0z = -2.0f * q0.z;
    const float a1x = -2.0f * q1.x, a1y = -2.0f * q1.y, a1z = -2.0f * q1.z;

    // sorted-across-lanes top-16 in e-space; li = POSITION in rc
    float ld = FLT_MAX; int li = 0;
    float wt0 = FLT_MAX, wt1 = FLT_MAX;

    // process a position range [start, end)
    auto process = [&](int start, int end) {
        for (int p = start; p < end; p += 32) {
            int pp = p + lane;
            bool valid = pp < end;
            float4 c = rc[valid ? pp : end - 1];
            float e0 = fmaf(a0x, c.x, fmaf(a0y, c.y, fmaf(a0z, c.z, c.w)));
            float e1 = fmaf(a1x, c.x, fmaf(a1y, c.y, fmaf(a1z, c.z, c.w)));
            unsigned bal0 = __ballot_sync(FULLM, valid && (e0 < wt0));
            unsigned bal1 = __ballot_sync(FULLM, valid && (e1 < wt1));
            if ((bal0 | bal1) == 0u) continue;
            do {
                int s0 = __ffs(bal0) - 1;
                int s1 = __ffs(bal1) - 1;
                float dd0 = __shfl_sync(FULLM, e0, s0 & 31);
                float dd1 = __shfl_sync(FULLM, e1, s1 & 31);
                bool have = g ? (bal1 != 0u) : (bal0 != 0u);
                float dd = g ? dd1 : dd0;
                int   jj = p + ((g ? s1 : s0) & 31);
                bool pr = have && (dd < ld);
                unsigned pb = __ballot_sync(FULLM, pr);
                float sld = __shfl_up_sync(FULLM, ld, 1);
                int   sli = __shfl_up_sync(FULLM, li, 1);
                bool prevpr = (sub > 0) && ((pb >> (lane - 1)) & 1u);
                if (pr) { ld = prevpr ? sld : dd; li = prevpr ? sli : jj; }
                bal0 &= bal0 - 1;
                bal1 &= bal1 - 1;
            } while (bal0 | bal1);
            wt0 = __shfl_sync(FULLM, ld, 15);
            wt1 = __shfl_sync(FULLM, ld, 31);
        }
    };

    // buckets of the two queries (binary search over off[], warp-uniform)
    int blo, bhi;
    {
        int lo = 0, hi = NBUCK - 1;
        while (lo < hi) { int mid = (lo + hi + 1) >> 1; if (off[mid] <= pos0) lo = mid; else hi = mid - 1; }
        blo = lo;
        lo = blo; hi = NBUCK - 1;
        int p1 = pos0 + 1;
        while (lo < hi) { int mid = (lo + hi + 1) >> 1; if (off[mid] <= p1) lo = mid; else hi = mid - 1; }
        bhi = lo;
    }

    process(off[blo], off[bhi + 1]);

    bool leftOpen = blo > 0, rightOpen = bhi < NBUCK - 1;
    while (leftOpen || rightOpen) {
        float r20 = (wt0 + q0.w) * 1.0001f + 1e-6f;   // d^2 bound, slack for fp
        float r21 = (wt1 + q1.w) * 1.0001f + 1e-6f;
        float LBx = XMIN + blo * BW;
        float RBx = XMIN + (bhi + 1) * BW;
        if (leftOpen) {
            float gl0 = fmaxf(q0.x - LBx - SAFE, 0.0f);
            float gl1 = fmaxf(q1.x - LBx - SAFE, 0.0f);
            if (gl0 * gl0 >= r20 && gl1 * gl1 >= r21) leftOpen = false;
        }
        if (rightOpen) {
            float gr0 = fmaxf(RBx - q0.x - SAFE, 0.0f);
            float gr1 = fmaxf(RBx - q1.x - SAFE, 0.0f);
            if (gr0 * gr0 >= r20 && gr1 * gr1 >= r21) rightOpen = false;
        }
        if (!(leftOpen || rightOpen)) break;
        bool goLeft = (leftOpen && rightOpen) ? ((q0.x - LBx) < (RBx - q1.x)) : leftOpen;
        if (goLeft) {
            blo--;
            process(off[blo], off[blo + 1]);
            leftOpen = blo > 0;
        } else {
            bhi++;
            process(off[bhi], off[bhi + 1]);
            rightOpen = bhi < NBUCK - 1;
        }
    }

    // epilogue: exact weight recomputation from coordinates (faithful to ref)
    const float4 qq = g ? q1 : q0;
    const float4 nbp = rc[li];
    float dx = qq.x - nbp.x, dy = qq.y - nbp.y, dz = qq.z - nbp.z;
    float dist2 = fmaf(dx, dx, fmaf(dy, dy, dz * dz));
    float w = expf(-0.5f * dist2);

    const int qorig = rid[pos0 + g];
    const int qglob = bN + qorig;
    g_idx[qglob * KNN_K + sub] = rid[li];
    g_w [qglob * KNN_K + sub] = w;

    float s = w;
    s += __shfl_xor_sync(FULLM, s, 8);
    s += __shfl_xor_sync(FULLM, s, 4);
    s += __shfl_xor_sync(FULLM, s, 2);
    s += __shfl_xor_sync(FULLM, s, 1);
    if (sub == 0) {
        g_Dfwd[qglob] = 0.5f * s;
        g_Drev[qglob] = 0ull;
    }
}

// Reverse-degree scatter with integer fixed-point atomics (deterministic).
__global__ void k_drev(int N, int total_edges)
{
    int e = blockIdx.x * blockDim.x + threadIdx.x;
    if (e >= total_edges) return;
    int q = e >> 4;                 // KNN_K == 16
    int b = q / N;
    float w = g_w[e];
    unsigned long long inc = (unsigned long long)((double)w * 4294967296.0);
    atomicAdd(&g_Drev[b * N + g_idx[e]], inc);
}

// Sparse Laplacian scatter.
__global__ void k_lap(float* __restrict__ out, int N, int total_edges)
{
    int e = blockIdx.x * blockDim.x + threadIdx.x;
    if (e >= total_edges) return;
    int q = e >> 4;
    int b = q / N;
    int i = q - b * N;
    int j = g_idx[e];
    float w = g_w[e];

    float Di = g_Dfwd[q]         + (float)((double)g_Drev[q]         * (0.5 / 4294967296.0));
    float Dj = g_Dfwd[b * N + j] + (float)((double)g_Drev[b * N + j] * (0.5 / 4294967296.0));
    float di = 1.0f / sqrtf(fmaxf(Di, 1e-6f));
    float dj = 1.0f / sqrtf(fmaxf(Dj, 1e-6f));
    float v = -((0.5f * w) * di) * dj;

    float* Lb = out + (size_t)b * N * (size_t)N;
    atomicAdd(Lb + (size_t)i * N + j, v);
    atomicAdd(Lb + (size_t)j * N + i, v);
}

extern "C" void kernel_launch(void* const* d_in, const int* in_sizes, int n_in,
                              void* d_out, int out_size)
{
    const float* xyz = (const float*)d_in[0];
    float* out = (float*)d_out;

    long long inel = in_sizes[0];                       // B*3*N
    int N = (int)((3LL * (long long)out_size) / inel);  // (3*B*N^2)/(3*B*N)
    int B = (int)(inel / (3LL * (long long)N));

    int pts = B * N;
    int pb = (pts + 255) / 256;
    k_hist<<<pb, 256>>>(xyz, N, B);
    k_scan<<<1, 32 * ((B + 0))>>>(B);
    k_reorder<<<pb, 256>>>(xyz, N, B);

    int nb_knn = B * (N / 32);        // KNN blocks (32 queries each)
    int nb_set = B * N;               // one block per output row
    size_t smem = (size_t)N * sizeof(float4) + (size_t)N * sizeof(unsigned short)
                + (size_t)(NBUCK + 1) * sizeof(int);

    cudaFuncSetAttribute(k_knn_init, cudaFuncAttributeMaxDynamicSharedMemorySize, (int)smem);
    k_knn_init<<<nb_knn + nb_set, TPB, smem>>>(out, N, B, nb_knn);

    int edges = B * N * KNN_K;
    int eb = (edges + 255) / 256;
    k_drev<<<eb, 256>>>(N, edges);
    k_lap<<<eb, 256>>>(out, N, edges);
}